// round 5
// baseline (speedup 1.0000x reference)
#include <cuda_runtime.h>

#define B_      1024
#define T_      8192
#define NW_     2048
#define NTH     512
#define HALF    4096
#define NSTAGE  2            // HALF / (NTH*4)
#define NCHUNK  1024         // chunks of 4 elems per half-row
#define NBLK    2048

__device__ float4       g_p4[NBLK];    // accR, accP, accW
__device__ float2       g_rs[NBLK];    // sp, sg per half-row
__device__ float2       g_bwa[B_];     // A's partial of the straddling word (x<0 => none)
__device__ float2       g_bwb[B_];     // B's partial of the straddling word
__device__ unsigned int g_count = 0;

__device__ __forceinline__ float wsumf(float v) {
#pragma unroll
    for (int o = 16; o > 0; o >>= 1) v += __shfl_down_sync(0xffffffffu, v, o);
    return v;
}
__device__ __forceinline__ double wsumd(double v) {
#pragma unroll
    for (int o = 16; o > 0; o >>= 1) v += __shfl_down_sync(0xffffffffu, v, o);
    return v;
}

__global__ void __launch_bounds__(NTH, 2) duration_loss_fused(
    const float* __restrict__ dur_pred,
    const float* __restrict__ dur_gt,
    const int*   __restrict__ ph2word,
    const int*   __restrict__ txt_tokens,
    float* __restrict__ out)
{
    __shared__ float2 s_tab[151];
    __shared__ float  s_wp[NW_], s_wg[NW_];
    __shared__ float  s_hp[NCHUNK], s_hg[NCHUNK];
    __shared__ int    s_hm[NCHUNK];
    __shared__ float  s_red[5][NTH / 32];
    __shared__ double s_dred[4][NTH / 32];
    __shared__ int    s_lo, s_hi, s_skip, s_islast;

    const int tid  = threadIdx.x;
    const int lane = tid & 31;
    const int wid  = tid >> 5;
    const int blk  = blockIdx.x;
    const int row  = blk >> 1;
    const int half = blk & 1;
    const int jbase = half * HALF;     // offset of this half within the row

    // token rule table: {expected_or_inf, is_ratio}
    for (int i = tid; i < 151; i += NTH) {
        float ex = 1e30f, rt = 0.0f;
        if (i == 94 || i == 100 || i == 92) ex = 2.0f;
        else if (i == 122)                  ex = 3.0f;
        else if (i == 43 || i == 27)        ex = 5.0f;
        if (i == 44 || i == 28 || i == 29 || i == 27 || i == 121 || i == 43) rt = 1.0f;
        s_tab[i] = make_float2(ex, rt);
    }
    for (int i = tid; i < NW_; i += NTH) { s_wp[i] = 0.0f; s_wg[i] = 0.0f; }

    const float* dpr = dur_pred   + (size_t)row * T_;
    const float* gtr = dur_gt     + (size_t)row * T_;
    const int*   wr  = ph2word    + (size_t)row * T_;
    const int*   tkr = txt_tokens + (size_t)row * T_;

    if (tid == 0) {
        s_lo = wr[jbase];
        s_hi = wr[jbase + HALF - 1];
        int skip = 0;
        if (half == 0 && wr[jbase + HALF - 1] == wr[jbase + HALF])
            skip = wr[jbase + HALF - 1];       // word straddles the split
        s_skip = skip;
    }
    __syncthreads();

    float accR = 0.0f, accP = 0.0f, sp = 0.0f, sg = 0.0f;
    int   defw[NSTAGE];
    float defp[NSTAGE], defg[NSTAGE];
    int   t0_wprev = -2, t0_w0 = -3;   // B-side straddle detection (tid 0 only)
#pragma unroll
    for (int s = 0; s < NSTAGE; ++s) { defw[s] = -1; defp[s] = 0.0f; defg[s] = 0.0f; }

#pragma unroll
    for (int s = 0; s < NSTAGE; ++s) {
        const int jr = jbase + s * (NTH * 4) + tid * 4;   // index within row

        const float4 dp4 = *reinterpret_cast<const float4*>(dpr + jr);
        const float4 gt4 = *reinterpret_cast<const float4*>(gtr + jr);
        const int4   tk4 = *reinterpret_cast<const int4*>(tkr + jr);
        const int4   w4  = *reinterpret_cast<const int4*>(wr  + jr);

        // neighbor values: shuffle for lanes 0..30, global for warp-edge lanes
        float dpn0 = __shfl_down_sync(0xffffffffu, dp4.x, 1);
        int   wn   = __shfl_down_sync(0xffffffffu, w4.x,  1);
        int   wprev = __shfl_up_sync(0xffffffffu, w4.w, 1);
        float dpn1l = 1e30f; int tknl = 150;
        if (lane == 31) {
            if (jr + 4 < T_) {
                dpn0  = dpr[jr + 4]; dpn1l = dpr[jr + 5];
                tknl  = tkr[jr + 4]; wn    = wr[jr + 4];
            } else {
                dpn0 = 1e30f; wn = -1;
            }
        }
        if (lane == 0) wprev = (jr > 0) ? wr[jr - 1] : -1;
        if (tid == 0 && s == 0) { t0_wprev = wprev; t0_w0 = w4.x; }

        float dpv[5] = { dp4.x, dp4.y, dp4.z, dp4.w, dpn0 };
        float gtv[4] = { gt4.x, gt4.y, gt4.z, gt4.w };
        int   tkv[4] = { tk4.x, tk4.y, tk4.z, tk4.w };
        int   wv[5]  = { w4.x,  w4.y,  w4.z,  w4.w,  wn  };

        // gap terms for own 4 elements; neighbor's first gap via shuffle of g[0]
        float g[5], sa[4];
#pragma unroll
        for (int k = 0; k < 4; ++k) {
            const float2 tb = s_tab[tkv[k]];
            const float g1 = fmaxf(dpv[k] - tb.x, 0.0f);
            const float g2 = fmaxf(dpv[k] - dpv[k + 1] * (1.0f / 3.0f), 0.0f) * tb.y;
            g[k]  = g1 + g2;
            sa[k] = (g2 > 0.0f) ? g2 : g1;
        }
        g[4] = __shfl_down_sync(0xffffffffu, g[0], 1);
        if (lane == 31) {
            const float2 tbn = s_tab[tknl];
            const float a = fmaxf(dpn0 - tbn.x, 0.0f);
            const float c = fmaxf(dpn0 - dpn1l * (1.0f / 3.0f), 0.0f) * tbn.y;
            g[4] = a + c;
        }

#pragma unroll
        for (int k = 0; k < 4; ++k) {
            const float rules = dpv[k] - sa[k] + g[k + 1];
            const float la = __log2f(dpv[k] + 1.0f);
            const float lr = __log2f(rules  + 1.0f);
            const float lg = __log2f(gtv[k] + 1.0f);
            const float dr = la - lr; accR = fmaf(dr, dr, accR);
            const float dq = la - lg; accP = fmaf(dq, dq, accP);
            sp += fmaxf(dpv[k], 0.0f);
            sg += gtv[k];
        }

        // ---- word-segment bookkeeping ----
        const int c = s * NTH + tid;
        float cp[4];
#pragma unroll
        for (int k = 0; k < 4; ++k) cp[k] = fmaxf(dpv[k], 0.0f);

        const bool e1 = (wv[1] == wv[0]);
        const bool e2 = e1 && (wv[2] == wv[0]);
        const bool e3 = e2 && (wv[3] == wv[0]);
        float hp = cp[0] + (e1 ? cp[1] : 0.0f) + (e2 ? cp[2] : 0.0f) + (e3 ? cp[3] : 0.0f);
        float hg = gtv[0] + (e1 ? gtv[1] : 0.0f) + (e2 ? gtv[2] : 0.0f) + (e3 ? gtv[3] : 0.0f);
        s_hp[c] = hp; s_hg[c] = hg;
        s_hm[c] = wv[0] | (e3 ? (int)0x80000000 : 0);

        // runs starting inside this chunk (unique writer per word)
        bool open = false; int rw = 0; float rp = 0.0f, rg = 0.0f;
        int pw = wprev;
#pragma unroll
        for (int k = 0; k < 4; ++k) {
            if (wv[k] != pw) {
                if (open) { s_wp[rw] = rp; s_wg[rw] = rg; }
                open = true; rw = wv[k]; rp = cp[k]; rg = gtv[k];
            } else if (open) {
                rp += cp[k]; rg += gtv[k];
            }
            pw = wv[k];
        }
        if (open) {
            if (wv[4] == rw) { defw[s] = rw; defp[s] = rp; defg[s] = rg; }
            else             { s_wp[rw] = rp; s_wg[rw] = rg; }
        }
    }
    __syncthreads();

    // resolve words spanning chunk boundaries (owner walks head-run chain)
#pragma unroll
    for (int s = 0; s < NSTAGE; ++s) {
        if (defw[s] >= 0) {
            const int w = defw[s];
            float p = defp[s], q = defg[s];
            int ci = s * NTH + tid + 1;
            while (ci < NCHUNK) {
                const int m = s_hm[ci];
                if ((m & 0x7fffffff) != w) break;
                p += s_hp[ci]; q += s_hg[ci];
                if (m >= 0) break;   // head run not full -> word ends here
                ++ci;
            }
            s_wp[w] = p; s_wg[w] = q;
        }
    }
    // B side: leading run continuing from A -> export partial, never into s_wp
    if (half == 1 && tid == 0 && t0_wprev == t0_w0) {
        const int w = t0_w0;
        float p = 0.0f, q = 0.0f;
        int ci = 0;
        while (ci < NCHUNK) {
            const int m = s_hm[ci];
            if ((m & 0x7fffffff) != w) break;
            p += s_hp[ci]; q += s_hg[ci];
            if (m >= 0) break;
            ++ci;
        }
        g_bwb[row] = make_float2(p, q);
    }
    __syncthreads();

    // A side: export straddling-word partial (accumulated in s_wp via defer walk)
    if (half == 0 && tid == 0) {
        const int sk = s_skip;
        g_bwa[row] = (sk > 0) ? make_float2(s_wp[sk], s_wg[sk])
                              : make_float2(-1.0f, 0.0f);
    }

    // word-level loss over this block's word range; skip straddling word on A
    float accW = 0.0f;
    {
        const int lo = s_lo, hi = s_hi, sk = s_skip;
        for (int w = lo + tid; w <= hi; w += NTH) {
            if (w > 0 && w != sk) {
                const float d = __log2f(s_wp[w] + 1.0f) - __log2f(s_wg[w] + 1.0f);
                accW = fmaf(d, d, accW);
            }
        }
    }

    // block reduction -> per-block partial
    float v[5] = { accR, accP, accW, sp, sg };
#pragma unroll
    for (int q = 0; q < 5; ++q) {
        const float r = wsumf(v[q]);
        if (lane == 0) s_red[q][wid] = r;
    }
    __syncthreads();
    if (wid == 0) {
        float t[5];
#pragma unroll
        for (int q = 0; q < 5; ++q) {
            float x = (lane < NTH / 32) ? s_red[q][lane] : 0.0f;
            t[q] = wsumf(x);
        }
        if (lane == 0) {
            g_p4[blk] = make_float4(t[0], t[1], t[2], 0.0f);
            g_rs[blk] = make_float2(t[3], t[4]);
            __threadfence();
            const unsigned tk = atomicAdd(&g_count, 1u);
            s_islast = (tk == (unsigned)(NBLK - 1));
        }
    }
    __syncthreads();

    if (s_islast) {
        __threadfence();
        double a0 = 0.0, a1 = 0.0, a2 = 0.0, a3 = 0.0;
        for (int i = tid; i < NBLK; i += NTH) {
            const float4 p = g_p4[i];
            a0 += p.x; a1 += p.y; a2 += p.z;
        }
        for (int r = tid; r < B_; r += NTH) {
            const float2 sA = g_rs[2 * r];
            const float2 sB = g_rs[2 * r + 1];
            const float ds = __log2f(sA.x + sB.x + 1.0f) - __log2f(sA.y + sB.y + 1.0f);
            a3 += (double)(ds * ds);
            const float2 wa = g_bwa[r];
            if (wa.x >= 0.0f) {   // straddling word: merged term
                const float2 wb = g_bwb[r];
                const float d = __log2f(wa.x + wb.x + 1.0f) - __log2f(wa.y + wb.y + 1.0f);
                a2 += (double)(d * d);
            }
        }
        double dv[4] = { a0, a1, a2, a3 };
#pragma unroll
        for (int q = 0; q < 4; ++q) {
            const double r = wsumd(dv[q]);
            if (lane == 0) s_dred[q][wid] = r;
        }
        __syncthreads();
        if (wid == 0) {
            double t[4];
#pragma unroll
            for (int q = 0; q < 4; ++q) {
                double x = (lane < NTH / 32) ? s_dred[q][lane] : 0.0;
                t[q] = wsumd(x);
            }
            if (lane == 0) {
                const double LN2SQ = 0.4804530139182014;   // ln(2)^2
                const double loss = LN2SQ * ((0.3 * t[0] + 0.6 * t[1]) / 8388608.0
                                           + 0.3 * t[2] / 2096128.0
                                           + 0.1 * t[3] / 1024.0);
                out[0] = (float)loss;
                g_count = 0;   // reset for next graph replay
            }
        }
    }
}

extern "C" void kernel_launch(void* const* d_in, const int* in_sizes, int n_in,
                              void* d_out, int out_size) {
    const float* dur_pred   = (const float*)d_in[0];
    const float* dur_gt     = (const float*)d_in[1];
    const int*   ph2word    = (const int*)d_in[2];
    const int*   txt_tokens = (const int*)d_in[3];
    duration_loss_fused<<<NBLK, NTH>>>(dur_pred, dur_gt, ph2word, txt_tokens, (float*)d_out);
}

// round 6
// speedup vs baseline: 1.2297x; 1.2297x over previous
#include <cuda_runtime.h>

#define B_      1024
#define T_      8192
#define NW_     2048
#define NTH     512
#define NSTAGE  4
#define NCHUNK  2048          // chunks of 4 elems per row

__device__ float4       g_part[B_];
__device__ unsigned int g_count = 0;

__device__ __forceinline__ float wsumf(float v) {
#pragma unroll
    for (int o = 16; o > 0; o >>= 1) v += __shfl_down_sync(0xffffffffu, v, o);
    return v;
}
__device__ __forceinline__ double wsumd(double v) {
#pragma unroll
    for (int o = 16; o > 0; o >>= 1) v += __shfl_down_sync(0xffffffffu, v, o);
    return v;
}

__global__ void __launch_bounds__(NTH, 2) duration_loss_fused(
    const float* __restrict__ dur_pred,
    const float* __restrict__ dur_gt,
    const int*   __restrict__ ph2word,
    const int*   __restrict__ txt_tokens,
    float* __restrict__ out)
{
    __shared__ float2 s_tab[151];
    __shared__ float2 s_w[NW_];          // packed {wdur_pred, wdur_gt}
    __shared__ float2 s_hv[NCHUNK];      // packed {head_pred, head_gt}
    __shared__ int    s_hm[NCHUNK];
    __shared__ float  s_red[5][NTH / 32];
    __shared__ double s_dred[4][NTH / 32];
    __shared__ int    s_islast;

    const int tid  = threadIdx.x;
    const int lane = tid & 31;
    const int wid  = tid >> 5;
    const int b    = blockIdx.x;

    // token rule table: {expected_or_inf, is_ratio}
    for (int i = tid; i < 151; i += NTH) {
        float ex = 1e30f, rt = 0.0f;
        if (i == 94 || i == 100 || i == 92) ex = 2.0f;
        else if (i == 122)                  ex = 3.0f;
        else if (i == 43 || i == 27)        ex = 5.0f;
        if (i == 44 || i == 28 || i == 29 || i == 27 || i == 121 || i == 43) rt = 1.0f;
        s_tab[i] = make_float2(ex, rt);
    }
    for (int i = tid; i < NW_; i += NTH) s_w[i] = make_float2(0.0f, 0.0f);
    __syncthreads();

    const float* dpr = dur_pred   + (size_t)b * T_;
    const float* gtr = dur_gt     + (size_t)b * T_;
    const int*   wr  = ph2word    + (size_t)b * T_;
    const int*   tkr = txt_tokens + (size_t)b * T_;

    float accR = 0.0f, accP = 0.0f, sp = 0.0f, sg = 0.0f;
    int   defw[NSTAGE];
    float defp[NSTAGE], defg[NSTAGE];
#pragma unroll
    for (int s = 0; s < NSTAGE; ++s) { defw[s] = -1; defp[s] = 0.0f; defg[s] = 0.0f; }

#pragma unroll
    for (int s = 0; s < NSTAGE; ++s) {
        const int j0 = s * (NTH * 4) + tid * 4;

        const float4 dp4 = *reinterpret_cast<const float4*>(dpr + j0);
        const float4 gt4 = *reinterpret_cast<const float4*>(gtr + j0);
        const int4   tk4 = *reinterpret_cast<const int4*>(tkr + j0);
        const int4   w4  = *reinterpret_cast<const int4*>(wr  + j0);

        // neighbor values: shuffle for lanes 0..30, global for warp-edge lanes
        float dpn0  = __shfl_down_sync(0xffffffffu, dp4.x, 1);
        int   wn    = __shfl_down_sync(0xffffffffu, w4.x,  1);
        int   wprev = __shfl_up_sync(0xffffffffu, w4.w, 1);
        float dpn1l = 1e30f; int tknl = 150;
        if (lane == 31) {
            if (j0 + 4 < T_) {
                dpn0  = dpr[j0 + 4]; dpn1l = dpr[j0 + 5];
                tknl  = tkr[j0 + 4]; wn    = wr[j0 + 4];
            } else {
                dpn0 = 1e30f; wn = -1;
            }
        }
        if (lane == 0) wprev = (j0 > 0) ? wr[j0 - 1] : -1;

        float dpv[5] = { dp4.x, dp4.y, dp4.z, dp4.w, dpn0 };
        float gtv[4] = { gt4.x, gt4.y, gt4.z, gt4.w };
        int   tkv[4] = { tk4.x, tk4.y, tk4.z, tk4.w };
        int   wv[5]  = { w4.x,  w4.y,  w4.z,  w4.w,  wn  };

        // gap terms for own 4 elements; neighbor's first gap via shuffle of g[0]
        float g[5], sa[4];
#pragma unroll
        for (int k = 0; k < 4; ++k) {
            const float2 tb = s_tab[tkv[k]];
            const float g1 = fmaxf(dpv[k] - tb.x, 0.0f);
            const float g2 = fmaxf(dpv[k] - dpv[k + 1] * (1.0f / 3.0f), 0.0f) * tb.y;
            g[k]  = g1 + g2;
            sa[k] = (g2 > 0.0f) ? g2 : g1;
        }
        g[4] = __shfl_down_sync(0xffffffffu, g[0], 1);
        if (lane == 31) {
            const float2 tbn = s_tab[tknl];
            const float a = fmaxf(dpn0 - tbn.x, 0.0f);
            const float c = fmaxf(dpn0 - dpn1l * (1.0f / 3.0f), 0.0f) * tbn.y;
            g[4] = a + c;
        }

#pragma unroll
        for (int k = 0; k < 4; ++k) {
            const float rules = dpv[k] - sa[k] + g[k + 1];
            const float la = __log2f(dpv[k] + 1.0f);
            const float lr = __log2f(rules  + 1.0f);
            const float lg = __log2f(gtv[k] + 1.0f);
            const float dr = la - lr; accR = fmaf(dr, dr, accR);
            const float dq = la - lg; accP = fmaf(dq, dq, accP);
            sp += fmaxf(dpv[k], 0.0f);
            sg += gtv[k];
        }

        // ---- word-segment bookkeeping ----
        const int c = s * NTH + tid;
        float cp[4];
#pragma unroll
        for (int k = 0; k < 4; ++k) cp[k] = fmaxf(dpv[k], 0.0f);

        const bool e1 = (wv[1] == wv[0]);
        const bool e2 = e1 && (wv[2] == wv[0]);
        const bool e3 = e2 && (wv[3] == wv[0]);
        float hp = cp[0] + (e1 ? cp[1] : 0.0f) + (e2 ? cp[2] : 0.0f) + (e3 ? cp[3] : 0.0f);
        float hg = gtv[0] + (e1 ? gtv[1] : 0.0f) + (e2 ? gtv[2] : 0.0f) + (e3 ? gtv[3] : 0.0f);
        s_hv[c] = make_float2(hp, hg);
        s_hm[c] = wv[0] | (e3 ? (int)0x80000000 : 0);

        // runs starting inside this chunk (unique writer per word)
        bool open = false; int rw = 0; float rp = 0.0f, rg = 0.0f;
        int pw = wprev;
#pragma unroll
        for (int k = 0; k < 4; ++k) {
            if (wv[k] != pw) {
                if (open) s_w[rw] = make_float2(rp, rg);
                open = true; rw = wv[k]; rp = cp[k]; rg = gtv[k];
            } else if (open) {
                rp += cp[k]; rg += gtv[k];
            }
            pw = wv[k];
        }
        if (open) {
            if (wv[4] == rw) { defw[s] = rw; defp[s] = rp; defg[s] = rg; }
            else             s_w[rw] = make_float2(rp, rg);
        }
    }
    __syncthreads();

    // resolve words spanning chunk boundaries (owner walks head-run chain)
#pragma unroll
    for (int s = 0; s < NSTAGE; ++s) {
        if (defw[s] >= 0) {
            const int w = defw[s];
            float p = defp[s], q = defg[s];
            int ci = s * NTH + tid + 1;
            while (ci < NCHUNK) {
                const int m = s_hm[ci];
                if ((m & 0x7fffffff) != w) break;
                const float2 hv = s_hv[ci];
                p += hv.x; q += hv.y;
                if (m >= 0) break;   // head run not full -> word ends here
                ++ci;
            }
            s_w[w] = make_float2(p, q);
        }
    }
    __syncthreads();

    // word-level loss (empty words give 0, word 0 excluded)
    float accW = 0.0f;
#pragma unroll
    for (int r = 0; r < NW_ / NTH; ++r) {
        const int w = r * NTH + tid;
        if (w > 0) {
            const float2 wv2 = s_w[w];
            const float d = __log2f(wv2.x + 1.0f) - __log2f(wv2.y + 1.0f);
            accW = fmaf(d, d, accW);
        }
    }

    // block reduction -> per-block partial
    float v[5] = { accR, accP, accW, sp, sg };
#pragma unroll
    for (int q = 0; q < 5; ++q) {
        const float r = wsumf(v[q]);
        if (lane == 0) s_red[q][wid] = r;
    }
    __syncthreads();
    if (wid == 0) {
        float t[5];
#pragma unroll
        for (int q = 0; q < 5; ++q) {
            float x = (lane < NTH / 32) ? s_red[q][lane] : 0.0f;
            t[q] = wsumf(x);
        }
        if (lane == 0) {
            const float ds = __log2f(t[3] + 1.0f) - __log2f(t[4] + 1.0f);
            g_part[b] = make_float4(t[0], t[1], t[2], ds * ds);
            __threadfence();
            const unsigned tk = atomicAdd(&g_count, 1u);
            s_islast = (tk == (unsigned)(gridDim.x - 1));
        }
    }
    __syncthreads();

    if (s_islast) {
        __threadfence();
        double a0 = 0.0, a1 = 0.0, a2 = 0.0, a3 = 0.0;
        for (int i = tid; i < B_; i += NTH) {
            const float4 p = g_part[i];
            a0 += p.x; a1 += p.y; a2 += p.z; a3 += p.w;
        }
        double dv[4] = { a0, a1, a2, a3 };
#pragma unroll
        for (int q = 0; q < 4; ++q) {
            const double r = wsumd(dv[q]);
            if (lane == 0) s_dred[q][wid] = r;
        }
        __syncthreads();
        if (wid == 0) {
            double t[4];
#pragma unroll
            for (int q = 0; q < 4; ++q) {
                double x = (lane < NTH / 32) ? s_dred[q][lane] : 0.0;
                t[q] = wsumd(x);
            }
            if (lane == 0) {
                const double LN2SQ = 0.4804530139182014;   // ln(2)^2
                const double loss = LN2SQ * ((0.3 * t[0] + 0.6 * t[1]) / 8388608.0
                                           + 0.3 * t[2] / 2096128.0
                                           + 0.1 * t[3] / 1024.0);
                out[0] = (float)loss;
                g_count = 0;   // reset for next graph replay
            }
        }
    }
}

extern "C" void kernel_launch(void* const* d_in, const int* in_sizes, int n_in,
                              void* d_out, int out_size) {
    const float* dur_pred   = (const float*)d_in[0];
    const float* dur_gt     = (const float*)d_in[1];
    const int*   ph2word    = (const int*)d_in[2];
    const int*   txt_tokens = (const int*)d_in[3];
    duration_loss_fused<<<B_, NTH>>>(dur_pred, dur_gt, ph2word, txt_tokens, (float*)d_out);
}